// round 1
// baseline (speedup 1.0000x reference)
#include <cuda_runtime.h>
#include <math.h>

#define BB    256
#define SS    512
#define OBS   64
#define ZD    16
#define HID   256
#define TPD   128      // T*PD
#define NITER 4
#define NEL   64
#define TILE  64
#define XROW  68       // padded smem row stride (floats)

// ---------------- device scratch (no allocs allowed) ----------------
__device__ float g_mu[BB * ZD];
__device__ float g_std[BB * ZD];
__device__ float g_best_score[BB];
__device__ float g_best_z[BB * ZD];
__device__ float g_score[BB * SS];
__device__ float g_z[(size_t)BB * SS * ZD];

// ---------------- encoder ----------------
__global__ void encoder_kernel(const float* __restrict__ s0,
                               const float* __restrict__ enc_w1, const float* __restrict__ enc_b1,
                               const float* __restrict__ enc_w2, const float* __restrict__ enc_b2,
                               const float* __restrict__ zmu_w,  const float* __restrict__ zmu_b,
                               const float* __restrict__ zls_w,  const float* __restrict__ zls_b)
{
    __shared__ float s0s[OBS];
    __shared__ float h1[HID];
    __shared__ float h2[HID];
    int b = blockIdx.x;
    int t = threadIdx.x;

    if (t < OBS) s0s[t] = s0[b * OBS + t];
    __syncthreads();

    float a = enc_b1[t];
    for (int k = 0; k < OBS; k++) a += s0s[k] * enc_w1[k * HID + t];
    h1[t] = fmaxf(a, 0.f);
    __syncthreads();

    a = enc_b2[t];
    for (int k = 0; k < HID; k++) a += h1[k] * enc_w2[k * HID + t];
    h2[t] = fmaxf(a, 0.f);
    __syncthreads();

    if (t < ZD) {
        float m = zmu_b[t], ls = zls_b[t];
        for (int k = 0; k < HID; k++) {
            float hv = h2[k];
            m  += hv * zmu_w[k * ZD + t];
            ls += hv * zls_w[k * ZD + t];
        }
        ls = fminf(fmaxf(ls, -4.f), 2.f);
        g_mu[b * ZD + t]     = m;
        g_std[b * ZD + t]    = expf(ls);
        g_best_z[b * ZD + t] = m;
    }
    if (t == 0) g_best_score[b] = -INFINITY;
}

// ---------------- fused tile GEMM: out[j][r] = act(bias[j] + sum_k xs[k][r]*W[k][j]) ----------------
__device__ __forceinline__ void gemm_tile(const float* __restrict__ xs,   // smem [K][XROW]
                                          int K,
                                          const float* __restrict__ W,    // global [K][256]
                                          const float* __restrict__ bias, // global [256]
                                          float* __restrict__ outbuf,     // smem [256][XROW]
                                          bool do_relu)
{
    int j = threadIdx.x;           // 0..255 : output column
    float acc[TILE];
    float bj = bias[j];
#pragma unroll
    for (int r = 0; r < TILE; r++) acc[r] = bj;

    float w = W[j];                // k=0 prefetch
    for (int k = 0; k < K; k++) {
        float wn = (k + 1 < K) ? W[(k + 1) * HID + j] : 0.f;
        const float4* xr = reinterpret_cast<const float4*>(xs + k * XROW);
#pragma unroll
        for (int r4 = 0; r4 < TILE / 4; r4++) {
            float4 v = xr[r4];
            acc[r4 * 4 + 0] += v.x * w;
            acc[r4 * 4 + 1] += v.y * w;
            acc[r4 * 4 + 2] += v.z * w;
            acc[r4 * 4 + 3] += v.w * w;
        }
        w = wn;
    }
    float* orow = outbuf + j * XROW;
#pragma unroll
    for (int r = 0; r < TILE; r++) {
        float v = acc[r];
        if (do_relu) v = fmaxf(v, 0.f);
        orow[r] = v;
    }
}

// ---------------- per-sample score ----------------
__global__ void score_kernel(int iter,
    const float* __restrict__ s0,  const float* __restrict__ eps,
    const float* __restrict__ mu_w1,  const float* __restrict__ mu_b1,
    const float* __restrict__ mu_w2,  const float* __restrict__ mu_b2,
    const float* __restrict__ mu_w3,  const float* __restrict__ mu_b3,
    const float* __restrict__ sig_w1, const float* __restrict__ sig_b1,
    const float* __restrict__ sig_w2, const float* __restrict__ sig_b2,
    const float* __restrict__ sig_w3, const float* __restrict__ sig_b3,
    const float* __restrict__ risk_w1, const float* __restrict__ risk_b1,
    const float* __restrict__ risk_w2, const float* __restrict__ risk_b2,
    const float* __restrict__ risk_w3, const float* __restrict__ risk_b3)
{
    extern __shared__ float smem[];
    float* xs   = smem;                       // [80][XROW]
    float* bufA = smem + 80 * XROW;           // [256][XROW]
    float* bufB = bufA + HID * XROW;          // [256][XROW]

    __shared__ float mu_s[ZD], std_s[ZD];
    __shared__ float m_s[2 * TILE];
    __shared__ float red_s[4 * TILE];
    __shared__ float intent_s[TILE], agency_s[TILE];

    int bidx   = blockIdx.x;
    int b      = bidx >> 3;                   // SS/TILE = 8
    int s_base = (bidx & 7) * TILE;
    int t      = threadIdx.x;

    if (t < ZD) { mu_s[t] = g_mu[b * ZD + t]; std_s[t] = g_std[b * ZD + t]; }
    __syncthreads();

    // stage x = [s0 | z] transposed into smem, write z to global
    for (int idx = t; idx < (OBS + ZD) * TILE; idx += 256) {
        int k = idx >> 6;
        int r = idx & 63;
        float v;
        if (k < OBS) {
            v = s0[b * OBS + k];
        } else {
            int d = k - OBS;
            int s = s_base + r;
            float e = eps[((((size_t)iter * BB + b) * SS) + s) * ZD + d];
            v = mu_s[d] + std_s[d] * e;
            g_z[((size_t)(b * SS + s)) * ZD + d] = v;
        }
        xs[k * XROW + r] = v;
    }
    __syncthreads();

    // ---- mu path ----
    gemm_tile(xs, OBS + ZD, mu_w1, mu_b1, bufA, true);
    __syncthreads();
    gemm_tile(bufA, HID, mu_w2, mu_b2, bufB, true);
    __syncthreads();
    if (t < 128) {                           // only last-timestep columns 126,127
        int r = t & 63;
        int c = (TPD - 2) + (t >> 6);
        float acc = mu_b3[c];
        for (int k = 0; k < HID; k++) acc += bufB[k * XROW + r] * mu_w3[k * TPD + c];
        m_s[(t >> 6) * TILE + r] = acc;
    }
    __syncthreads();
    if (t < TILE) {
        float g0 = xs[2 * XROW + t];         // s0[b][2] (broadcast value)
        float g1 = xs[3 * XROW + t];         // s0[b][3]
        float d0 = m_s[t] - g0;
        float d1 = m_s[TILE + t] - g1;
        intent_s[t] = d0 * d0 + d1 * d1;
    }
    __syncthreads();

    // ---- sigma path (input = z rows of xs) ----
    gemm_tile(xs + OBS * XROW, ZD, sig_w1, sig_b1, bufA, true);
    __syncthreads();
    gemm_tile(bufA, HID, sig_w2, sig_b2, bufB, true);
    __syncthreads();
    if (t < TPD) {                            // 128 output columns, clip, stash in bufA
        int j = t;
        float acc[TILE];
        float bj = sig_b3[j];
#pragma unroll
        for (int r = 0; r < TILE; r++) acc[r] = bj;
        for (int k = 0; k < HID; k++) {
            float w = sig_w3[k * TPD + j];
            const float4* xr = reinterpret_cast<const float4*>(bufB + k * XROW);
#pragma unroll
            for (int r4 = 0; r4 < TILE / 4; r4++) {
                float4 v = xr[r4];
                acc[r4 * 4 + 0] += v.x * w;
                acc[r4 * 4 + 1] += v.y * w;
                acc[r4 * 4 + 2] += v.z * w;
                acc[r4 * 4 + 3] += v.w * w;
            }
        }
        float* orow = bufA + j * XROW;
#pragma unroll
        for (int r = 0; r < TILE; r++) orow[r] = fminf(fmaxf(acc[r], -4.f), 3.f);
    }
    __syncthreads();
    {
        int r = t & 63, g = t >> 6;
        float sum = 0.f;
        for (int j = g * 32; j < g * 32 + 32; j++) sum += bufA[j * XROW + r];
        red_s[g * TILE + r] = sum;
    }
    __syncthreads();
    if (t < TILE) {
        float sum = red_s[t] + red_s[TILE + t] + red_s[2 * TILE + t] + red_s[3 * TILE + t];
        agency_s[t] = -sum * (1.f / TPD);
    }
    __syncthreads();

    // ---- risk path ----
    gemm_tile(xs, OBS + ZD, risk_w1, risk_b1, bufA, true);
    __syncthreads();
    gemm_tile(bufA, HID, risk_w2, risk_b2, bufB, true);
    __syncthreads();
    if (t < TILE) {
        int r = t;
        float acc = risk_b3[0];
        for (int k = 0; k < HID; k++) acc += bufB[k * XROW + r] * risk_w3[k];
        float risk = 1.f / (1.f + expf(-acc));
        float score = -intent_s[r] + 0.5f * agency_s[r] - risk;
        g_score[b * SS + s_base + r] = score;
    }
}

// ---------------- top-k + CEM update ----------------
__global__ void topk_kernel(int write_out, float* __restrict__ out)
{
    __shared__ float keys[SS];
    __shared__ int   ids[SS];
    __shared__ float ps[16 * ZD];
    __shared__ float mean_s[ZD];
    __shared__ int   flag_s, bidx_s;

    int b = blockIdx.x;
    int t = threadIdx.x;

    keys[t]       = g_score[b * SS + t];       ids[t]       = t;
    keys[t + 256] = g_score[b * SS + t + 256]; ids[t + 256] = t + 256;

    // bitonic sort ascending (512 elems, 256 threads)
    for (int k2 = 2; k2 <= SS; k2 <<= 1)
        for (int j = k2 >> 1; j > 0; j >>= 1) {
            __syncthreads();
            int i = ((t & ~(j - 1)) << 1) | (t & (j - 1));
            int p = i | j;
            bool up = ((i & k2) == 0);
            float a = keys[i], c = keys[p];
            if ((a > c) == up) {
                keys[i] = c; keys[p] = a;
                int tmp = ids[i]; ids[i] = ids[p]; ids[p] = tmp;
            }
        }
    __syncthreads();

    // elite mean (top-64 = positions [448, 512))
    int d = t & 15, part = t >> 4;
    float sum = 0.f;
    for (int e = part * 4; e < part * 4 + 4; e++) {
        int si = ids[SS - NEL + e];
        sum += g_z[((size_t)(b * SS + si)) * ZD + d];
    }
    ps[part * ZD + d] = sum;
    __syncthreads();
    if (t < ZD) {
        float m = 0.f;
        for (int p2 = 0; p2 < 16; p2++) m += ps[p2 * ZD + t];
        mean_s[t] = m * (1.f / NEL);
    }
    __syncthreads();

    // elite var (ddof=1)
    sum = 0.f;
    for (int e = part * 4; e < part * 4 + 4; e++) {
        int si = ids[SS - NEL + e];
        float v = g_z[((size_t)(b * SS + si)) * ZD + d] - mean_s[d];
        sum += v * v;
    }
    ps[part * ZD + d] = sum;
    __syncthreads();

    if (t == 0) {
        float v0 = keys[SS - 1];
        int better = v0 > g_best_score[b];
        flag_s = better; bidx_s = ids[SS - 1];
        if (better) g_best_score[b] = v0;
    }
    __syncthreads();

    if (t < ZD) {
        float var  = 0.f;
        for (int p2 = 0; p2 < 16; p2++) var += ps[p2 * ZD + t];
        float nstd = sqrtf(var * (1.f / (NEL - 1)));
        float nmu  = mean_s[t];
        float om = g_mu[b * ZD + t], os = g_std[b * ZD + t];
        g_mu[b * ZD + t]  = 0.25f * om + 0.75f * nmu;
        g_std[b * ZD + t] = fmaxf(0.25f * os + 0.75f * nstd, 0.2f);
        if (flag_s) g_best_z[b * ZD + t] = g_z[((size_t)(b * SS + bidx_s)) * ZD + t];
    }

    if (write_out) {
        __syncthreads();
        if (t < ZD)  out[b * 17 + t]  = g_best_z[b * ZD + t];
        if (t == ZD) out[b * 17 + ZD] = g_best_score[b];
    }
}

// ---------------- launch ----------------
extern "C" void kernel_launch(void* const* d_in, const int* in_sizes, int n_in,
                              void* d_out, int out_size)
{
    const float* s0      = (const float*)d_in[0];
    const float* eps     = (const float*)d_in[1];
    const float* enc_w1  = (const float*)d_in[2];
    const float* enc_b1  = (const float*)d_in[3];
    const float* enc_w2  = (const float*)d_in[4];
    const float* enc_b2  = (const float*)d_in[5];
    const float* zmu_w   = (const float*)d_in[6];
    const float* zmu_b   = (const float*)d_in[7];
    const float* zls_w   = (const float*)d_in[8];
    const float* zls_b   = (const float*)d_in[9];
    const float* mu_w1   = (const float*)d_in[10];
    const float* mu_b1   = (const float*)d_in[11];
    const float* mu_w2   = (const float*)d_in[12];
    const float* mu_b2   = (const float*)d_in[13];
    const float* mu_w3   = (const float*)d_in[14];
    const float* mu_b3   = (const float*)d_in[15];
    const float* sig_w1  = (const float*)d_in[16];
    const float* sig_b1  = (const float*)d_in[17];
    const float* sig_w2  = (const float*)d_in[18];
    const float* sig_b2  = (const float*)d_in[19];
    const float* sig_w3  = (const float*)d_in[20];
    const float* sig_b3  = (const float*)d_in[21];
    const float* risk_w1 = (const float*)d_in[22];
    const float* risk_b1 = (const float*)d_in[23];
    const float* risk_w2 = (const float*)d_in[24];
    const float* risk_b2 = (const float*)d_in[25];
    const float* risk_w3 = (const float*)d_in[26];
    const float* risk_b3 = (const float*)d_in[27];

    const int SMEM_BYTES = (80 + 2 * HID) * XROW * (int)sizeof(float);  // 161,024 B
    cudaFuncSetAttribute(score_kernel, cudaFuncAttributeMaxDynamicSharedMemorySize, SMEM_BYTES);

    encoder_kernel<<<BB, 256>>>(s0, enc_w1, enc_b1, enc_w2, enc_b2,
                                zmu_w, zmu_b, zls_w, zls_b);

    for (int i = 0; i < NITER; i++) {
        score_kernel<<<BB * (SS / TILE), 256, SMEM_BYTES>>>(i, s0, eps,
            mu_w1, mu_b1, mu_w2, mu_b2, mu_w3, mu_b3,
            sig_w1, sig_b1, sig_w2, sig_b2, sig_w3, sig_b3,
            risk_w1, risk_b1, risk_w2, risk_b2, risk_w3, risk_b3);
        topk_kernel<<<BB, 256>>>(i == NITER - 1 ? 1 : 0, (float*)d_out);
    }
}

// round 2
// speedup vs baseline: 1.3687x; 1.3687x over previous
#include <cuda_runtime.h>
#include <math.h>

#define BB    256
#define SS    512
#define OBS   64
#define ZD    16
#define HID   256
#define TPD   128      // T*PD
#define NITER 4
#define NEL   64
#define TILE  32
#define XROW  36       // padded smem row stride (floats), multiple of 4 for float4

// ---------------- device scratch (no allocs allowed) ----------------
__device__ float g_mu[BB * ZD];
__device__ float g_std[BB * ZD];
__device__ float g_best_score[BB];
__device__ float g_best_z[BB * ZD];
__device__ float g_score[BB * SS];
__device__ float g_z[(size_t)BB * SS * ZD];

// ---------------- encoder ----------------
__global__ void encoder_kernel(const float* __restrict__ s0,
                               const float* __restrict__ enc_w1, const float* __restrict__ enc_b1,
                               const float* __restrict__ enc_w2, const float* __restrict__ enc_b2,
                               const float* __restrict__ zmu_w,  const float* __restrict__ zmu_b,
                               const float* __restrict__ zls_w,  const float* __restrict__ zls_b)
{
    __shared__ float s0s[OBS];
    __shared__ float h1[HID];
    __shared__ float h2[HID];
    int b = blockIdx.x;
    int t = threadIdx.x;

    if (t < OBS) s0s[t] = s0[b * OBS + t];
    __syncthreads();

    float a = enc_b1[t];
    for (int k = 0; k < OBS; k++) a += s0s[k] * enc_w1[k * HID + t];
    h1[t] = fmaxf(a, 0.f);
    __syncthreads();

    a = enc_b2[t];
    for (int k = 0; k < HID; k++) a += h1[k] * enc_w2[k * HID + t];
    h2[t] = fmaxf(a, 0.f);
    __syncthreads();

    if (t < ZD) {
        float m = zmu_b[t], ls = zls_b[t];
        for (int k = 0; k < HID; k++) {
            float hv = h2[k];
            m  += hv * zmu_w[k * ZD + t];
            ls += hv * zls_w[k * ZD + t];
        }
        ls = fminf(fmaxf(ls, -4.f), 2.f);
        g_mu[b * ZD + t]     = m;
        g_std[b * ZD + t]    = expf(ls);
        g_best_z[b * ZD + t] = m;
    }
    if (t == 0) g_best_score[b] = -INFINITY;
}

// ---------------- fused tile GEMM: out[j][r] = act(bias[j] + sum_k xs[k][r]*W[k][j]) ----------------
__device__ __forceinline__ void gemm_tile(const float* __restrict__ xs,   // smem [K][XROW]
                                          int K,
                                          const float* __restrict__ W,    // global [K][256]
                                          const float* __restrict__ bias, // global [256]
                                          float* __restrict__ outbuf,     // smem [256][XROW]
                                          bool do_relu)
{
    int j = threadIdx.x;           // 0..255 : output column
    float acc[TILE];
    float bj = bias[j];
#pragma unroll
    for (int r = 0; r < TILE; r++) acc[r] = bj;

    float w = W[j];                // k=0 prefetch
    for (int k = 0; k < K; k++) {
        float wn = (k + 1 < K) ? W[(k + 1) * HID + j] : 0.f;
        const float4* xr = reinterpret_cast<const float4*>(xs + k * XROW);
#pragma unroll
        for (int r4 = 0; r4 < TILE / 4; r4++) {
            float4 v = xr[r4];
            acc[r4 * 4 + 0] += v.x * w;
            acc[r4 * 4 + 1] += v.y * w;
            acc[r4 * 4 + 2] += v.z * w;
            acc[r4 * 4 + 3] += v.w * w;
        }
        w = wn;
    }
    float* orow = outbuf + j * XROW;
#pragma unroll
    for (int r = 0; r < TILE; r++) {
        float v = acc[r];
        if (do_relu) v = fmaxf(v, 0.f);
        orow[r] = v;
    }
}

// ---------------- per-sample score ----------------
__global__ void __launch_bounds__(256, 2) score_kernel(int iter,
    const float* __restrict__ s0,  const float* __restrict__ eps,
    const float* __restrict__ mu_w1,  const float* __restrict__ mu_b1,
    const float* __restrict__ mu_w2,  const float* __restrict__ mu_b2,
    const float* __restrict__ mu_w3,  const float* __restrict__ mu_b3,
    const float* __restrict__ sig_w1, const float* __restrict__ sig_b1,
    const float* __restrict__ sig_w2, const float* __restrict__ sig_b2,
    const float* __restrict__ sig_w3, const float* __restrict__ sig_b3,
    const float* __restrict__ risk_w1, const float* __restrict__ risk_b1,
    const float* __restrict__ risk_w2, const float* __restrict__ risk_b2,
    const float* __restrict__ risk_w3, const float* __restrict__ risk_b3)
{
    extern __shared__ float smem[];
    float* xs   = smem;                       // [80][XROW]
    float* bufA = smem + 80 * XROW;           // [256][XROW]
    float* bufB = bufA + HID * XROW;          // [256][XROW]

    __shared__ float mu_s[ZD], std_s[ZD];
    __shared__ float m_s[2 * TILE];
    __shared__ float red_s[8 * TILE];
    __shared__ float intent_s[TILE], agency_s[TILE];
    __shared__ float mu3c0[HID], mu3c1[HID], rw3[HID];

    int bidx   = blockIdx.x;
    int b      = bidx >> 4;                   // SS/TILE = 16
    int s_base = (bidx & 15) * TILE;
    int t      = threadIdx.x;

    if (t < ZD) { mu_s[t] = g_mu[b * ZD + t]; std_s[t] = g_std[b * ZD + t]; }
    __syncthreads();

    // stage x = [s0 | z] transposed into smem, write z to global
    for (int idx = t; idx < (OBS + ZD) * TILE; idx += 256) {
        int k = idx >> 5;
        int r = idx & 31;
        float v;
        if (k < OBS) {
            v = s0[b * OBS + k];
        } else {
            int d = k - OBS;
            int s = s_base + r;
            float e = eps[((((size_t)iter * BB + b) * SS) + s) * ZD + d];
            v = mu_s[d] + std_s[d] * e;
            g_z[((size_t)(b * SS + s)) * ZD + d] = v;
        }
        xs[k * XROW + r] = v;
    }
    // preload strided head weights into smem (one per thread)
    mu3c0[t] = mu_w3[t * TPD + (TPD - 2)];
    mu3c1[t] = mu_w3[t * TPD + (TPD - 1)];
    rw3[t]   = risk_w3[t];
    __syncthreads();

    // ---- mu path ----
    gemm_tile(xs, OBS + ZD, mu_w1, mu_b1, bufA, true);
    __syncthreads();
    gemm_tile(bufA, HID, mu_w2, mu_b2, bufB, true);
    __syncthreads();
    if (t < 2 * TILE) {                       // only last-timestep columns 126,127
        int r = t & (TILE - 1);
        int c = t >> 5;                       // 0 or 1
        const float* wc = c ? mu3c1 : mu3c0;
        float acc = mu_b3[(TPD - 2) + c];
        for (int k = 0; k < HID; k++) acc += bufB[k * XROW + r] * wc[k];
        m_s[c * TILE + r] = acc;
    }
    __syncthreads();
    if (t < TILE) {
        float g0 = xs[2 * XROW + t];          // s0[b][2] (broadcast value)
        float g1 = xs[3 * XROW + t];          // s0[b][3]
        float d0 = m_s[t] - g0;
        float d1 = m_s[TILE + t] - g1;
        intent_s[t] = d0 * d0 + d1 * d1;
    }
    __syncthreads();

    // ---- sigma path (input = z rows of xs) ----
    gemm_tile(xs + OBS * XROW, ZD, sig_w1, sig_b1, bufA, true);
    __syncthreads();
    gemm_tile(bufA, HID, sig_w2, sig_b2, bufB, true);
    __syncthreads();
    {   // layer3: 128 output columns x 32 rows, all 256 threads (each does 16 rows)
        int j    = t & (TPD - 1);
        int half = t >> 7;                    // 0 or 1 -> rows [half*16, half*16+16)
        float acc[TILE / 2];
        float bj = sig_b3[j];
#pragma unroll
        for (int r = 0; r < TILE / 2; r++) acc[r] = bj;
        for (int k = 0; k < HID; k++) {
            float w = sig_w3[k * TPD + j];
            const float4* xr = reinterpret_cast<const float4*>(bufB + k * XROW + half * (TILE / 2));
#pragma unroll
            for (int r4 = 0; r4 < TILE / 8; r4++) {
                float4 v = xr[r4];
                acc[r4 * 4 + 0] += v.x * w;
                acc[r4 * 4 + 1] += v.y * w;
                acc[r4 * 4 + 2] += v.z * w;
                acc[r4 * 4 + 3] += v.w * w;
            }
        }
        float* orow = bufA + j * XROW + half * (TILE / 2);
#pragma unroll
        for (int r = 0; r < TILE / 2; r++) orow[r] = fminf(fmaxf(acc[r], -4.f), 3.f);
    }
    __syncthreads();
    {   // reduce over 128 columns: 8 groups of 16 columns
        int r = t & (TILE - 1), g = t >> 5;
        float sum = 0.f;
        for (int j = g * 16; j < g * 16 + 16; j++) sum += bufA[j * XROW + r];
        red_s[g * TILE + r] = sum;
    }
    __syncthreads();
    if (t < TILE) {
        float sum = 0.f;
#pragma unroll
        for (int g = 0; g < 8; g++) sum += red_s[g * TILE + t];
        agency_s[t] = -sum * (1.f / TPD);
    }
    __syncthreads();

    // ---- risk path ----
    gemm_tile(xs, OBS + ZD, risk_w1, risk_b1, bufA, true);
    __syncthreads();
    gemm_tile(bufA, HID, risk_w2, risk_b2, bufB, true);
    __syncthreads();
    if (t < TILE) {
        int r = t;
        float acc = risk_b3[0];
        for (int k = 0; k < HID; k++) acc += bufB[k * XROW + r] * rw3[k];
        float risk = 1.f / (1.f + expf(-acc));
        float score = -intent_s[r] + 0.5f * agency_s[r] - risk;
        g_score[b * SS + s_base + r] = score;
    }
}

// ---------------- top-k + CEM update ----------------
__global__ void topk_kernel(int write_out, float* __restrict__ out)
{
    __shared__ float keys[SS];
    __shared__ int   ids[SS];
    __shared__ float ps[16 * ZD];
    __shared__ float mean_s[ZD];
    __shared__ int   flag_s, bidx_s;

    int b = blockIdx.x;
    int t = threadIdx.x;

    keys[t]       = g_score[b * SS + t];       ids[t]       = t;
    keys[t + 256] = g_score[b * SS + t + 256]; ids[t + 256] = t + 256;

    // bitonic sort ascending (512 elems, 256 threads)
    for (int k2 = 2; k2 <= SS; k2 <<= 1)
        for (int j = k2 >> 1; j > 0; j >>= 1) {
            __syncthreads();
            int i = ((t & ~(j - 1)) << 1) | (t & (j - 1));
            int p = i | j;
            bool up = ((i & k2) == 0);
            float a = keys[i], c = keys[p];
            if ((a > c) == up) {
                keys[i] = c; keys[p] = a;
                int tmp = ids[i]; ids[i] = ids[p]; ids[p] = tmp;
            }
        }
    __syncthreads();

    // elite mean (top-64 = positions [448, 512))
    int d = t & 15, part = t >> 4;
    float sum = 0.f;
    for (int e = part * 4; e < part * 4 + 4; e++) {
        int si = ids[SS - NEL + e];
        sum += g_z[((size_t)(b * SS + si)) * ZD + d];
    }
    ps[part * ZD + d] = sum;
    __syncthreads();
    if (t < ZD) {
        float m = 0.f;
        for (int p2 = 0; p2 < 16; p2++) m += ps[p2 * ZD + t];
        mean_s[t] = m * (1.f / NEL);
    }
    __syncthreads();

    // elite var (ddof=1)
    sum = 0.f;
    for (int e = part * 4; e < part * 4 + 4; e++) {
        int si = ids[SS - NEL + e];
        float v = g_z[((size_t)(b * SS + si)) * ZD + d] - mean_s[d];
        sum += v * v;
    }
    ps[part * ZD + d] = sum;
    __syncthreads();

    if (t == 0) {
        float v0 = keys[SS - 1];
        int better = v0 > g_best_score[b];
        flag_s = better; bidx_s = ids[SS - 1];
        if (better) g_best_score[b] = v0;
    }
    __syncthreads();

    if (t < ZD) {
        float var  = 0.f;
        for (int p2 = 0; p2 < 16; p2++) var += ps[p2 * ZD + t];
        float nstd = sqrtf(var * (1.f / (NEL - 1)));
        float nmu  = mean_s[t];
        float om = g_mu[b * ZD + t], os = g_std[b * ZD + t];
        g_mu[b * ZD + t]  = 0.25f * om + 0.75f * nmu;
        g_std[b * ZD + t] = fmaxf(0.25f * os + 0.75f * nstd, 0.2f);
        if (flag_s) g_best_z[b * ZD + t] = g_z[((size_t)(b * SS + bidx_s)) * ZD + t];
    }

    if (write_out) {
        __syncthreads();
        if (t < ZD)  out[b * 17 + t]  = g_best_z[b * ZD + t];
        if (t == ZD) out[b * 17 + ZD] = g_best_score[b];
    }
}

// ---------------- launch ----------------
extern "C" void kernel_launch(void* const* d_in, const int* in_sizes, int n_in,
                              void* d_out, int out_size)
{
    const float* s0      = (const float*)d_in[0];
    const float* eps     = (const float*)d_in[1];
    const float* enc_w1  = (const float*)d_in[2];
    const float* enc_b1  = (const float*)d_in[3];
    const float* enc_w2  = (const float*)d_in[4];
    const float* enc_b2  = (const float*)d_in[5];
    const float* zmu_w   = (const float*)d_in[6];
    const float* zmu_b   = (const float*)d_in[7];
    const float* zls_w   = (const float*)d_in[8];
    const float* zls_b   = (const float*)d_in[9];
    const float* mu_w1   = (const float*)d_in[10];
    const float* mu_b1   = (const float*)d_in[11];
    const float* mu_w2   = (const float*)d_in[12];
    const float* mu_b2   = (const float*)d_in[13];
    const float* mu_w3   = (const float*)d_in[14];
    const float* mu_b3   = (const float*)d_in[15];
    const float* sig_w1  = (const float*)d_in[16];
    const float* sig_b1  = (const float*)d_in[17];
    const float* sig_w2  = (const float*)d_in[18];
    const float* sig_b2  = (const float*)d_in[19];
    const float* sig_w3  = (const float*)d_in[20];
    const float* sig_b3  = (const float*)d_in[21];
    const float* risk_w1 = (const float*)d_in[22];
    const float* risk_b1 = (const float*)d_in[23];
    const float* risk_w2 = (const float*)d_in[24];
    const float* risk_b2 = (const float*)d_in[25];
    const float* risk_w3 = (const float*)d_in[26];
    const float* risk_b3 = (const float*)d_in[27];

    const int SMEM_BYTES = (80 + 2 * HID) * XROW * (int)sizeof(float);  // 85,248 B
    cudaFuncSetAttribute(score_kernel, cudaFuncAttributeMaxDynamicSharedMemorySize, SMEM_BYTES);

    encoder_kernel<<<BB, 256>>>(s0, enc_w1, enc_b1, enc_w2, enc_b2,
                                zmu_w, zmu_b, zls_w, zls_b);

    for (int i = 0; i < NITER; i++) {
        score_kernel<<<BB * (SS / TILE), 256, SMEM_BYTES>>>(i, s0, eps,
            mu_w1, mu_b1, mu_w2, mu_b2, mu_w3, mu_b3,
            sig_w1, sig_b1, sig_w2, sig_b2, sig_w3, sig_b3,
            risk_w1, risk_b1, risk_w2, risk_b2, risk_w3, risk_b3);
        topk_kernel<<<BB, 256>>>(i == NITER - 1 ? 1 : 0, (float*)d_out);
    }
}

// round 3
// speedup vs baseline: 1.8303x; 1.3373x over previous
#include <cuda_runtime.h>
#include <math.h>

#define BB    256
#define SS    512
#define OBS   64
#define ZD    16
#define HID   256
#define TPD   128      // T*PD
#define NITER 4
#define NEL   64
#define TILE  32
#define XROW  36       // padded smem row stride (floats), multiple of 4

// ---- packed f32x2 helpers ----
#define PACK2(dst, lo, hi) asm("mov.b64 %0, {%1, %2};" : "=l"(dst) : "f"(lo), "f"(hi))
#define UNPACK2(lo, hi, src) asm("mov.b64 {%0, %1}, %2;" : "=f"(lo), "=f"(hi) : "l"(src))
#define FMA2(acc, a, b) asm("fma.rn.f32x2 %0, %1, %2, %0;" : "+l"(acc) : "l"(a), "l"(b))

// ---------------- device scratch (no allocs allowed) ----------------
__device__ float g_mu[BB * ZD];
__device__ float g_std[BB * ZD];
__device__ float g_best_score[BB];
__device__ float g_best_z[BB * ZD];
__device__ float g_score[BB * SS];
__device__ float g_z[(size_t)BB * SS * ZD];

// ---------------- encoder ----------------
__global__ void encoder_kernel(const float* __restrict__ s0,
                               const float* __restrict__ enc_w1, const float* __restrict__ enc_b1,
                               const float* __restrict__ enc_w2, const float* __restrict__ enc_b2,
                               const float* __restrict__ zmu_w,  const float* __restrict__ zmu_b,
                               const float* __restrict__ zls_w,  const float* __restrict__ zls_b)
{
    __shared__ float s0s[OBS];
    __shared__ float h1[HID];
    __shared__ float h2[HID];
    int b = blockIdx.x;
    int t = threadIdx.x;

    if (t < OBS) s0s[t] = s0[b * OBS + t];
    __syncthreads();

    float a = enc_b1[t];
    for (int k = 0; k < OBS; k++) a += s0s[k] * enc_w1[k * HID + t];
    h1[t] = fmaxf(a, 0.f);
    __syncthreads();

    a = enc_b2[t];
    for (int k = 0; k < HID; k++) a += h1[k] * enc_w2[k * HID + t];
    h2[t] = fmaxf(a, 0.f);
    __syncthreads();

    if (t < ZD) {
        float m = zmu_b[t], ls = zls_b[t];
        for (int k = 0; k < HID; k++) {
            float hv = h2[k];
            m  += hv * zmu_w[k * ZD + t];
            ls += hv * zls_w[k * ZD + t];
        }
        ls = fminf(fmaxf(ls, -4.f), 2.f);
        g_mu[b * ZD + t]     = m;
        g_std[b * ZD + t]    = expf(ls);
        g_best_z[b * ZD + t] = m;
    }
    if (t == 0) g_best_score[b] = -INFINITY;
}

// ---------------- fused tile GEMM (packed f32x2 accumulate) ----------------
// out[j][r] = act(bias[j] + sum_k xs[k][r]*W[k][j])
template<int K, bool DO_RELU>
__device__ __forceinline__ void gemm_tile(const float* __restrict__ xs,   // smem [K][XROW]
                                          const float* __restrict__ W,    // global [K][256]
                                          const float* __restrict__ bias, // global [256]
                                          float* __restrict__ outbuf)     // smem [256][XROW]
{
    const int j = threadIdx.x;
    unsigned long long acc2[TILE / 2];
    float bj = bias[j];
    unsigned long long bj2; PACK2(bj2, bj, bj);
#pragma unroll
    for (int r = 0; r < TILE / 2; r++) acc2[r] = bj2;

    constexpr int PF = 4;                    // K is always a multiple of 4 here
    float w[PF];
#pragma unroll
    for (int p = 0; p < PF; p++) w[p] = W[p * HID + j];

#pragma unroll 4
    for (int k = 0; k < K; k++) {
        float wc = w[k % PF];
        int kn = k + PF;
        if (kn < K) w[k % PF] = W[kn * HID + j];
        unsigned long long w2; PACK2(w2, wc, wc);
        const ulonglong2* xr = reinterpret_cast<const ulonglong2*>(xs + k * XROW);
#pragma unroll
        for (int r4 = 0; r4 < TILE / 4; r4++) {
            ulonglong2 v = xr[r4];
            FMA2(acc2[r4 * 2 + 0], v.x, w2);
            FMA2(acc2[r4 * 2 + 1], v.y, w2);
        }
    }
    float* orow = outbuf + j * XROW;
#pragma unroll
    for (int r2 = 0; r2 < TILE / 2; r2++) {
        float lo, hi; UNPACK2(lo, hi, acc2[r2]);
        if (DO_RELU) { lo = fmaxf(lo, 0.f); hi = fmaxf(hi, 0.f); }
        orow[r2 * 2 + 0] = lo;
        orow[r2 * 2 + 1] = hi;
    }
}

// ---------------- per-sample score ----------------
__global__ void __launch_bounds__(256, 2) score_kernel(int iter,
    const float* __restrict__ s0,  const float* __restrict__ eps,
    const float* __restrict__ mu_w1,  const float* __restrict__ mu_b1,
    const float* __restrict__ mu_w2,  const float* __restrict__ mu_b2,
    const float* __restrict__ mu_w3,  const float* __restrict__ mu_b3,
    const float* __restrict__ sig_w1, const float* __restrict__ sig_b1,
    const float* __restrict__ sig_w2, const float* __restrict__ sig_b2,
    const float* __restrict__ sig_w3, const float* __restrict__ sig_b3,
    const float* __restrict__ risk_w1, const float* __restrict__ risk_b1,
    const float* __restrict__ risk_w2, const float* __restrict__ risk_b2,
    const float* __restrict__ risk_w3, const float* __restrict__ risk_b3)
{
    extern __shared__ float smem[];
    float* xs   = smem;                       // [80][XROW]
    float* bufA = smem + 80 * XROW;           // [256][XROW]
    float* bufB = bufA + HID * XROW;          // [256][XROW]

    __shared__ float mu_s[ZD], std_s[ZD];
    __shared__ float m_s[2 * TILE];
    __shared__ float red_s[8 * TILE];
    __shared__ float intent_s[TILE], agency_s[TILE];
    __shared__ float mu3c0[HID], mu3c1[HID], rw3[HID];

    int bidx   = blockIdx.x;
    int b      = bidx >> 4;                   // SS/TILE = 16
    int s_base = (bidx & 15) * TILE;
    int t      = threadIdx.x;

    if (t < ZD) { mu_s[t] = g_mu[b * ZD + t]; std_s[t] = g_std[b * ZD + t]; }
    __syncthreads();

    // stage x = [s0 | z] transposed into smem, write z to global
    for (int idx = t; idx < (OBS + ZD) * TILE; idx += 256) {
        int k = idx >> 5;
        int r = idx & 31;
        float v;
        if (k < OBS) {
            v = s0[b * OBS + k];
        } else {
            int d = k - OBS;
            int s = s_base + r;
            float e = eps[((((size_t)iter * BB + b) * SS) + s) * ZD + d];
            v = mu_s[d] + std_s[d] * e;
            g_z[((size_t)(b * SS + s)) * ZD + d] = v;
        }
        xs[k * XROW + r] = v;
    }
    // preload strided head weights into smem (one per thread)
    mu3c0[t] = mu_w3[t * TPD + (TPD - 2)];
    mu3c1[t] = mu_w3[t * TPD + (TPD - 1)];
    rw3[t]   = risk_w3[t];
    __syncthreads();

    // ---- mu path ----
    gemm_tile<OBS + ZD, true>(xs, mu_w1, mu_b1, bufA);
    __syncthreads();
    gemm_tile<HID, true>(bufA, mu_w2, mu_b2, bufB);
    __syncthreads();
    if (t < 2 * TILE) {                       // only last-timestep columns 126,127
        int r = t & (TILE - 1);
        int c = t >> 5;                       // 0 or 1
        const float* wc = c ? mu3c1 : mu3c0;
        float acc = mu_b3[(TPD - 2) + c];
        for (int k = 0; k < HID; k++) acc += bufB[k * XROW + r] * wc[k];
        m_s[c * TILE + r] = acc;
    }
    __syncthreads();
    if (t < TILE) {
        float g0 = xs[2 * XROW + t];          // s0[b][2] (broadcast value)
        float g1 = xs[3 * XROW + t];          // s0[b][3]
        float d0 = m_s[t] - g0;
        float d1 = m_s[TILE + t] - g1;
        intent_s[t] = d0 * d0 + d1 * d1;
    }
    __syncthreads();

    // ---- sigma path (input = z rows of xs) ----
    gemm_tile<ZD, true>(xs + OBS * XROW, sig_w1, sig_b1, bufA);
    __syncthreads();
    gemm_tile<HID, true>(bufA, sig_w2, sig_b2, bufB);
    __syncthreads();
    {   // layer3: 128 output columns x 32 rows, all 256 threads (each does 16 rows)
        int j    = t & (TPD - 1);
        int half = t >> 7;                    // 0 or 1 -> rows [half*16, half*16+16)
        const float* base = bufB + half * (TILE / 2);
        unsigned long long acc2[TILE / 4];
        float bj = sig_b3[j];
        unsigned long long bj2; PACK2(bj2, bj, bj);
#pragma unroll
        for (int r = 0; r < TILE / 4; r++) acc2[r] = bj2;

        constexpr int PF = 4;
        float w[PF];
#pragma unroll
        for (int p = 0; p < PF; p++) w[p] = sig_w3[p * TPD + j];

#pragma unroll 4
        for (int k = 0; k < HID; k++) {
            float wc = w[k % PF];
            int kn = k + PF;
            if (kn < HID) w[k % PF] = sig_w3[kn * TPD + j];
            unsigned long long w2; PACK2(w2, wc, wc);
            const ulonglong2* xr = reinterpret_cast<const ulonglong2*>(base + k * XROW);
#pragma unroll
            for (int r4 = 0; r4 < TILE / 8; r4++) {
                ulonglong2 v = xr[r4];
                FMA2(acc2[r4 * 2 + 0], v.x, w2);
                FMA2(acc2[r4 * 2 + 1], v.y, w2);
            }
        }
        float* orow = bufA + j * XROW + half * (TILE / 2);
#pragma unroll
        for (int r2 = 0; r2 < TILE / 4; r2++) {
            float lo, hi; UNPACK2(lo, hi, acc2[r2]);
            orow[r2 * 2 + 0] = fminf(fmaxf(lo, -4.f), 3.f);
            orow[r2 * 2 + 1] = fminf(fmaxf(hi, -4.f), 3.f);
        }
    }
    __syncthreads();
    {   // reduce over 128 columns: 8 groups of 16 columns
        int r = t & (TILE - 1), g = t >> 5;
        float sum = 0.f;
        for (int j = g * 16; j < g * 16 + 16; j++) sum += bufA[j * XROW + r];
        red_s[g * TILE + r] = sum;
    }
    __syncthreads();
    if (t < TILE) {
        float sum = 0.f;
#pragma unroll
        for (int g = 0; g < 8; g++) sum += red_s[g * TILE + t];
        agency_s[t] = -sum * (1.f / TPD);
    }
    __syncthreads();

    // ---- risk path ----
    gemm_tile<OBS + ZD, true>(xs, risk_w1, risk_b1, bufA);
    __syncthreads();
    gemm_tile<HID, true>(bufA, risk_w2, risk_b2, bufB);
    __syncthreads();
    if (t < TILE) {
        int r = t;
        float acc = risk_b3[0];
        for (int k = 0; k < HID; k++) acc += bufB[k * XROW + r] * rw3[k];
        float risk = 1.f / (1.f + expf(-acc));
        float score = -intent_s[r] + 0.5f * agency_s[r] - risk;
        g_score[b * SS + s_base + r] = score;
    }
}

// ---------------- top-k + CEM update ----------------
__global__ void topk_kernel(int write_out, float* __restrict__ out)
{
    __shared__ float keys[SS];
    __shared__ int   ids[SS];
    __shared__ float ps[16 * ZD];
    __shared__ float mean_s[ZD];
    __shared__ int   flag_s, bidx_s;

    int b = blockIdx.x;
    int t = threadIdx.x;

    keys[t]       = g_score[b * SS + t];       ids[t]       = t;
    keys[t + 256] = g_score[b * SS + t + 256]; ids[t + 256] = t + 256;

    // bitonic sort ascending (512 elems, 256 threads)
    for (int k2 = 2; k2 <= SS; k2 <<= 1)
        for (int j = k2 >> 1; j > 0; j >>= 1) {
            __syncthreads();
            int i = ((t & ~(j - 1)) << 1) | (t & (j - 1));
            int p = i | j;
            bool up = ((i & k2) == 0);
            float a = keys[i], c = keys[p];
            if ((a > c) == up) {
                keys[i] = c; keys[p] = a;
                int tmp = ids[i]; ids[i] = ids[p]; ids[p] = tmp;
            }
        }
    __syncthreads();

    // elite mean (top-64 = positions [448, 512))
    int d = t & 15, part = t >> 4;
    float sum = 0.f;
    for (int e = part * 4; e < part * 4 + 4; e++) {
        int si = ids[SS - NEL + e];
        sum += g_z[((size_t)(b * SS + si)) * ZD + d];
    }
    ps[part * ZD + d] = sum;
    __syncthreads();
    if (t < ZD) {
        float m = 0.f;
        for (int p2 = 0; p2 < 16; p2++) m += ps[p2 * ZD + t];
        mean_s[t] = m * (1.f / NEL);
    }
    __syncthreads();

    // elite var (ddof=1)
    sum = 0.f;
    for (int e = part * 4; e < part * 4 + 4; e++) {
        int si = ids[SS - NEL + e];
        float v = g_z[((size_t)(b * SS + si)) * ZD + d] - mean_s[d];
        sum += v * v;
    }
    ps[part * ZD + d] = sum;
    __syncthreads();

    if (t == 0) {
        float v0 = keys[SS - 1];
        int better = v0 > g_best_score[b];
        flag_s = better; bidx_s = ids[SS - 1];
        if (better) g_best_score[b] = v0;
    }
    __syncthreads();

    if (t < ZD) {
        float var  = 0.f;
        for (int p2 = 0; p2 < 16; p2++) var += ps[p2 * ZD + t];
        float nstd = sqrtf(var * (1.f / (NEL - 1)));
        float nmu  = mean_s[t];
        float om = g_mu[b * ZD + t], os = g_std[b * ZD + t];
        g_mu[b * ZD + t]  = 0.25f * om + 0.75f * nmu;
        g_std[b * ZD + t] = fmaxf(0.25f * os + 0.75f * nstd, 0.2f);
        if (flag_s) g_best_z[b * ZD + t] = g_z[((size_t)(b * SS + bidx_s)) * ZD + t];
    }

    if (write_out) {
        __syncthreads();
        if (t < ZD)  out[b * 17 + t]  = g_best_z[b * ZD + t];
        if (t == ZD) out[b * 17 + ZD] = g_best_score[b];
    }
}

// ---------------- launch ----------------
extern "C" void kernel_launch(void* const* d_in, const int* in_sizes, int n_in,
                              void* d_out, int out_size)
{
    const float* s0      = (const float*)d_in[0];
    const float* eps     = (const float*)d_in[1];
    const float* enc_w1  = (const float*)d_in[2];
    const float* enc_b1  = (const float*)d_in[3];
    const float* enc_w2  = (const float*)d_in[4];
    const float* enc_b2  = (const float*)d_in[5];
    const float* zmu_w   = (const float*)d_in[6];
    const float* zmu_b   = (const float*)d_in[7];
    const float* zls_w   = (const float*)d_in[8];
    const float* zls_b   = (const float*)d_in[9];
    const float* mu_w1   = (const float*)d_in[10];
    const float* mu_b1   = (const float*)d_in[11];
    const float* mu_w2   = (const float*)d_in[12];
    const float* mu_b2   = (const float*)d_in[13];
    const float* mu_w3   = (const float*)d_in[14];
    const float* mu_b3   = (const float*)d_in[15];
    const float* sig_w1  = (const float*)d_in[16];
    const float* sig_b1  = (const float*)d_in[17];
    const float* sig_w2  = (const float*)d_in[18];
    const float* sig_b2  = (const float*)d_in[19];
    const float* sig_w3  = (const float*)d_in[20];
    const float* sig_b3  = (const float*)d_in[21];
    const float* risk_w1 = (const float*)d_in[22];
    const float* risk_b1 = (const float*)d_in[23];
    const float* risk_w2 = (const float*)d_in[24];
    const float* risk_b2 = (const float*)d_in[25];
    const float* risk_w3 = (const float*)d_in[26];
    const float* risk_b3 = (const float*)d_in[27];

    const int SMEM_BYTES = (80 + 2 * HID) * XROW * (int)sizeof(float);  // 85,248 B
    cudaFuncSetAttribute(score_kernel, cudaFuncAttributeMaxDynamicSharedMemorySize, SMEM_BYTES);

    encoder_kernel<<<BB, 256>>>(s0, enc_w1, enc_b1, enc_w2, enc_b2,
                                zmu_w, zmu_b, zls_w, zls_b);

    for (int i = 0; i < NITER; i++) {
        score_kernel<<<BB * (SS / TILE), 256, SMEM_BYTES>>>(i, s0, eps,
            mu_w1, mu_b1, mu_w2, mu_b2, mu_w3, mu_b3,
            sig_w1, sig_b1, sig_w2, sig_b2, sig_w3, sig_b3,
            risk_w1, risk_b1, risk_w2, risk_b2, risk_w3, risk_b3);
        topk_kernel<<<BB, 256>>>(i == NITER - 1 ? 1 : 0, (float*)d_out);
    }
}

// round 4
// speedup vs baseline: 2.4410x; 1.3337x over previous
#include <cuda_runtime.h>
#include <math.h>

#define BB    256
#define SS    512
#define OBS   64
#define ZD    16
#define HID   256
#define TPD   128      // T*PD
#define NITER 4
#define NEL   64
#define TILE  32
#define XROW  36       // padded smem row stride (floats), multiple of 4

// ---- packed f32x2 helpers ----
#define PACK2(dst, lo, hi) asm("mov.b64 %0, {%1, %2};" : "=l"(dst) : "f"(lo), "f"(hi))
#define UNPACK2(lo, hi, src) asm("mov.b64 {%0, %1}, %2;" : "=f"(lo), "=f"(hi) : "l"(src))
#define FMA2(acc, a, b) asm("fma.rn.f32x2 %0, %1, %2, %0;" : "+l"(acc) : "l"(a), "l"(b))

// ---------------- device scratch (no allocs allowed) ----------------
__device__ float g_mu[BB * ZD];
__device__ float g_std[BB * ZD];
__device__ float g_best_score[BB];
__device__ float g_best_z[BB * ZD];
__device__ float g_score[BB * SS];
__device__ float g_z[(size_t)BB * SS * ZD];

// ---------------- encoder ----------------
__global__ void encoder_kernel(const float* __restrict__ s0,
                               const float* __restrict__ enc_w1, const float* __restrict__ enc_b1,
                               const float* __restrict__ enc_w2, const float* __restrict__ enc_b2,
                               const float* __restrict__ zmu_w,  const float* __restrict__ zmu_b,
                               const float* __restrict__ zls_w,  const float* __restrict__ zls_b)
{
    __shared__ float s0s[OBS];
    __shared__ float h1[HID];
    __shared__ float h2[HID];
    int b = blockIdx.x;
    int t = threadIdx.x;

    if (t < OBS) s0s[t] = s0[b * OBS + t];
    __syncthreads();

    float a = enc_b1[t];
    for (int k = 0; k < OBS; k++) a += s0s[k] * enc_w1[k * HID + t];
    h1[t] = fmaxf(a, 0.f);
    __syncthreads();

    a = enc_b2[t];
    for (int k = 0; k < HID; k++) a += h1[k] * enc_w2[k * HID + t];
    h2[t] = fmaxf(a, 0.f);
    __syncthreads();

    if (t < ZD) {
        float m = zmu_b[t], ls = zls_b[t];
        for (int k = 0; k < HID; k++) {
            float hv = h2[k];
            m  += hv * zmu_w[k * ZD + t];
            ls += hv * zls_w[k * ZD + t];
        }
        ls = fminf(fmaxf(ls, -4.f), 2.f);
        g_mu[b * ZD + t]     = m;
        g_std[b * ZD + t]    = expf(ls);
        g_best_z[b * ZD + t] = m;
    }
    if (t == 0) g_best_score[b] = -INFINITY;
}

// ---------------- fused tile GEMM, 2 cols x 16 rows per thread ----------------
// out[j][r] = act(bias[j] + sum_k xs[k][r]*W[k][j])
template<int K, bool DO_RELU>
__device__ __forceinline__ void gemm_tile2(const float* __restrict__ xs,   // smem [K][XROW]
                                           const float* __restrict__ W,    // global [K][256]
                                           const float* __restrict__ bias, // global [256]
                                           float* __restrict__ outbuf)     // smem [256][XROW]
{
    const int t    = threadIdx.x;
    const int j0   = t & 127;
    const int j1   = j0 + 128;
    const int half = t >> 7;                  // rows [half*16, half*16+16)
    const float* xbase = xs + half * 16;

    unsigned long long accA[8], accB[8];
    {
        float b0 = bias[j0], b1 = bias[j1];
        unsigned long long b02, b12; PACK2(b02, b0, b0); PACK2(b12, b1, b1);
#pragma unroll
        for (int r = 0; r < 8; r++) { accA[r] = b02; accB[r] = b12; }
    }

    constexpr int PF = 4;                     // K multiple of 4
    float wa[PF], wb[PF];
#pragma unroll
    for (int p = 0; p < PF; p++) { wa[p] = W[p * HID + j0]; wb[p] = W[p * HID + j1]; }

#pragma unroll 4
    for (int k = 0; k < K; k++) {
        float wca = wa[k % PF], wcb = wb[k % PF];
        int kn = k + PF;
        if (kn < K) { wa[k % PF] = W[kn * HID + j0]; wb[k % PF] = W[kn * HID + j1]; }
        unsigned long long w2a, w2b; PACK2(w2a, wca, wca); PACK2(w2b, wcb, wcb);
        const ulonglong2* xr = reinterpret_cast<const ulonglong2*>(xbase + k * XROW);
#pragma unroll
        for (int r4 = 0; r4 < 4; r4++) {
            ulonglong2 v = xr[r4];
            FMA2(accA[r4 * 2 + 0], v.x, w2a);
            FMA2(accA[r4 * 2 + 1], v.y, w2a);
            FMA2(accB[r4 * 2 + 0], v.x, w2b);
            FMA2(accB[r4 * 2 + 1], v.y, w2b);
        }
    }

    float* o0 = outbuf + j0 * XROW + half * 16;
    float* o1 = outbuf + j1 * XROW + half * 16;
#pragma unroll
    for (int r2 = 0; r2 < 8; r2++) {
        float lo, hi;
        UNPACK2(lo, hi, accA[r2]);
        if (DO_RELU) { lo = fmaxf(lo, 0.f); hi = fmaxf(hi, 0.f); }
        o0[r2 * 2 + 0] = lo; o0[r2 * 2 + 1] = hi;
        UNPACK2(lo, hi, accB[r2]);
        if (DO_RELU) { lo = fmaxf(lo, 0.f); hi = fmaxf(hi, 0.f); }
        o1[r2 * 2 + 0] = lo; o1[r2 * 2 + 1] = hi;
    }
}

// ---------------- per-sample score ----------------
__global__ void __launch_bounds__(256, 2) score_kernel(int iter,
    const float* __restrict__ s0,  const float* __restrict__ eps,
    const float* __restrict__ mu_w1,  const float* __restrict__ mu_b1,
    const float* __restrict__ mu_w2,  const float* __restrict__ mu_b2,
    const float* __restrict__ mu_w3,  const float* __restrict__ mu_b3,
    const float* __restrict__ sig_w1, const float* __restrict__ sig_b1,
    const float* __restrict__ sig_w2, const float* __restrict__ sig_b2,
    const float* __restrict__ sig_w3, const float* __restrict__ sig_b3,
    const float* __restrict__ risk_w1, const float* __restrict__ risk_b1,
    const float* __restrict__ risk_w2, const float* __restrict__ risk_b2,
    const float* __restrict__ risk_w3, const float* __restrict__ risk_b3)
{
    extern __shared__ float smem[];
    float* xs   = smem;                       // [80][XROW]
    float* bufA = smem + 80 * XROW;           // [256][XROW]
    float* bufB = bufA + HID * XROW;          // [256][XROW]

    __shared__ float mu_s[ZD], std_s[ZD];
    __shared__ float m_s[2 * TILE];
    __shared__ float red_s[8 * TILE];
    __shared__ float intent_s[TILE], agency_s[TILE];
    __shared__ float mu3c0[HID], mu3c1[HID], rw3[HID];

    int bidx   = blockIdx.x;
    int b      = bidx >> 4;                   // SS/TILE = 16
    int s_base = (bidx & 15) * TILE;
    int t      = threadIdx.x;

    if (t < ZD) { mu_s[t] = g_mu[b * ZD + t]; std_s[t] = g_std[b * ZD + t]; }
    __syncthreads();

    // stage x = [s0 | z] transposed into smem, write z to global
    for (int idx = t; idx < (OBS + ZD) * TILE; idx += 256) {
        int k = idx >> 5;
        int r = idx & 31;
        float v;
        if (k < OBS) {
            v = s0[b * OBS + k];
        } else {
            int d = k - OBS;
            int s = s_base + r;
            float e = eps[((((size_t)iter * BB + b) * SS) + s) * ZD + d];
            v = mu_s[d] + std_s[d] * e;
            g_z[((size_t)(b * SS + s)) * ZD + d] = v;
        }
        xs[k * XROW + r] = v;
    }
    // preload strided head weights into smem (one per thread)
    mu3c0[t] = mu_w3[t * TPD + (TPD - 2)];
    mu3c1[t] = mu_w3[t * TPD + (TPD - 1)];
    rw3[t]   = risk_w3[t];
    __syncthreads();

    // ---- mu path ----
    gemm_tile2<OBS + ZD, true>(xs, mu_w1, mu_b1, bufA);
    __syncthreads();
    gemm_tile2<HID, true>(bufA, mu_w2, mu_b2, bufB);
    __syncthreads();
    {   // layer3 (cols 126,127 only): 64 outputs, split k over 4 parts
        int r = t & 31, c = (t >> 5) & 1, part = t >> 6;
        const float* wc = c ? mu3c1 : mu3c0;
        float acc = 0.f;
        int k0 = part * 64;
        for (int k = k0; k < k0 + 64; k++) acc += bufB[k * XROW + r] * wc[k];
        red_s[t] = acc;
    }
    __syncthreads();
    if (t < 2 * TILE) {
        int r = t & 31, c = t >> 5;
        float acc = mu_b3[(TPD - 2) + c] + red_s[t] + red_s[t + 64] + red_s[t + 128] + red_s[t + 192];
        m_s[c * TILE + r] = acc;
    }
    __syncthreads();
    if (t < TILE) {
        float g0 = xs[2 * XROW + t];          // s0[b][2] (broadcast value)
        float g1 = xs[3 * XROW + t];          // s0[b][3]
        float d0 = m_s[t] - g0;
        float d1 = m_s[TILE + t] - g1;
        intent_s[t] = d0 * d0 + d1 * d1;
    }
    __syncthreads();

    // ---- sigma path (input = z rows of xs) ----
    gemm_tile2<ZD, true>(xs + OBS * XROW, sig_w1, sig_b1, bufA);
    __syncthreads();
    gemm_tile2<HID, true>(bufA, sig_w2, sig_b2, bufB);
    __syncthreads();
    {   // layer3: 128 cols x 32 rows; 2 cols x 8 rows per thread
        int j0 = t & 63;
        int j1 = j0 + 64;
        int q  = t >> 6;                      // rows [q*8, q*8+8)
        const float* base = bufB + q * 8;
        unsigned long long accA[4], accB[4];
        {
            float b0 = sig_b3[j0], b1 = sig_b3[j1];
            unsigned long long b02, b12; PACK2(b02, b0, b0); PACK2(b12, b1, b1);
#pragma unroll
            for (int r = 0; r < 4; r++) { accA[r] = b02; accB[r] = b12; }
        }
        constexpr int PF = 4;
        float wa[PF], wb[PF];
#pragma unroll
        for (int p = 0; p < PF; p++) { wa[p] = sig_w3[p * TPD + j0]; wb[p] = sig_w3[p * TPD + j1]; }
#pragma unroll 4
        for (int k = 0; k < HID; k++) {
            float wca = wa[k % PF], wcb = wb[k % PF];
            int kn = k + PF;
            if (kn < HID) { wa[k % PF] = sig_w3[kn * TPD + j0]; wb[k % PF] = sig_w3[kn * TPD + j1]; }
            unsigned long long w2a, w2b; PACK2(w2a, wca, wca); PACK2(w2b, wcb, wcb);
            const ulonglong2* xr = reinterpret_cast<const ulonglong2*>(base + k * XROW);
#pragma unroll
            for (int r4 = 0; r4 < 2; r4++) {
                ulonglong2 v = xr[r4];
                FMA2(accA[r4 * 2 + 0], v.x, w2a);
                FMA2(accA[r4 * 2 + 1], v.y, w2a);
                FMA2(accB[r4 * 2 + 0], v.x, w2b);
                FMA2(accB[r4 * 2 + 1], v.y, w2b);
            }
        }
        float* o0 = bufA + j0 * XROW + q * 8;
        float* o1 = bufA + j1 * XROW + q * 8;
#pragma unroll
        for (int r2 = 0; r2 < 4; r2++) {
            float lo, hi;
            UNPACK2(lo, hi, accA[r2]);
            o0[r2 * 2 + 0] = fminf(fmaxf(lo, -4.f), 3.f);
            o0[r2 * 2 + 1] = fminf(fmaxf(hi, -4.f), 3.f);
            UNPACK2(lo, hi, accB[r2]);
            o1[r2 * 2 + 0] = fminf(fmaxf(lo, -4.f), 3.f);
            o1[r2 * 2 + 1] = fminf(fmaxf(hi, -4.f), 3.f);
        }
    }
    __syncthreads();
    {   // reduce over 128 columns: 8 groups of 16 columns
        int r = t & (TILE - 1), g = t >> 5;
        float sum = 0.f;
        for (int j = g * 16; j < g * 16 + 16; j++) sum += bufA[j * XROW + r];
        red_s[g * TILE + r] = sum;
    }
    __syncthreads();
    if (t < TILE) {
        float sum = 0.f;
#pragma unroll
        for (int g = 0; g < 8; g++) sum += red_s[g * TILE + t];
        agency_s[t] = -sum * (1.f / TPD);
    }
    __syncthreads();

    // ---- risk path ----
    gemm_tile2<OBS + ZD, true>(xs, risk_w1, risk_b1, bufA);
    __syncthreads();
    gemm_tile2<HID, true>(bufA, risk_w2, risk_b2, bufB);
    __syncthreads();
    {   // layer3: 32 outputs, k split over 8 parts
        int r = t & 31, part = t >> 5;
        float acc = 0.f;
        int k0 = part * 32;
        for (int k = k0; k < k0 + 32; k++) acc += bufB[k * XROW + r] * rw3[k];
        red_s[t] = acc;
    }
    __syncthreads();
    if (t < TILE) {
        float acc = risk_b3[0];
#pragma unroll
        for (int p = 0; p < 8; p++) acc += red_s[t + p * 32];
        float risk = 1.f / (1.f + expf(-acc));
        float score = -intent_s[t] + 0.5f * agency_s[t] - risk;
        g_score[b * SS + s_base + t] = score;
    }
}

// ---------------- top-k + CEM update ----------------
__global__ void topk_kernel(int write_out, float* __restrict__ out)
{
    __shared__ float keys[SS];
    __shared__ int   ids[SS];
    __shared__ float ps[16 * ZD];
    __shared__ float mean_s[ZD];
    __shared__ int   flag_s, bidx_s;

    int b = blockIdx.x;
    int t = threadIdx.x;

    keys[t]       = g_score[b * SS + t];       ids[t]       = t;
    keys[t + 256] = g_score[b * SS + t + 256]; ids[t + 256] = t + 256;

    // bitonic sort ascending (512 elems, 256 threads)
    for (int k2 = 2; k2 <= SS; k2 <<= 1)
        for (int j = k2 >> 1; j > 0; j >>= 1) {
            __syncthreads();
            int i = ((t & ~(j - 1)) << 1) | (t & (j - 1));
            int p = i | j;
            bool up = ((i & k2) == 0);
            float a = keys[i], c = keys[p];
            if ((a > c) == up) {
                keys[i] = c; keys[p] = a;
                int tmp = ids[i]; ids[i] = ids[p]; ids[p] = tmp;
            }
        }
    __syncthreads();

    // elite mean (top-64 = positions [448, 512))
    int d = t & 15, part = t >> 4;
    float sum = 0.f;
    for (int e = part * 4; e < part * 4 + 4; e++) {
        int si = ids[SS - NEL + e];
        sum += g_z[((size_t)(b * SS + si)) * ZD + d];
    }
    ps[part * ZD + d] = sum;
    __syncthreads();
    if (t < ZD) {
        float m = 0.f;
        for (int p2 = 0; p2 < 16; p2++) m += ps[p2 * ZD + t];
        mean_s[t] = m * (1.f / NEL);
    }
    __syncthreads();

    // elite var (ddof=1)
    sum = 0.f;
    for (int e = part * 4; e < part * 4 + 4; e++) {
        int si = ids[SS - NEL + e];
        float v = g_z[((size_t)(b * SS + si)) * ZD + d] - mean_s[d];
        sum += v * v;
    }
    ps[part * ZD + d] = sum;
    __syncthreads();

    if (t == 0) {
        float v0 = keys[SS - 1];
        int better = v0 > g_best_score[b];
        flag_s = better; bidx_s = ids[SS - 1];
        if (better) g_best_score[b] = v0;
    }
    __syncthreads();

    if (t < ZD) {
        float var  = 0.f;
        for (int p2 = 0; p2 < 16; p2++) var += ps[p2 * ZD + t];
        float nstd = sqrtf(var * (1.f / (NEL - 1)));
        float nmu  = mean_s[t];
        float om = g_mu[b * ZD + t], os = g_std[b * ZD + t];
        g_mu[b * ZD + t]  = 0.25f * om + 0.75f * nmu;
        g_std[b * ZD + t] = fmaxf(0.25f * os + 0.75f * nstd, 0.2f);
        if (flag_s) g_best_z[b * ZD + t] = g_z[((size_t)(b * SS + bidx_s)) * ZD + t];
    }

    if (write_out) {
        __syncthreads();
        if (t < ZD)  out[b * 17 + t]  = g_best_z[b * ZD + t];
        if (t == ZD) out[b * 17 + ZD] = g_best_score[b];
    }
}

// ---------------- launch ----------------
extern "C" void kernel_launch(void* const* d_in, const int* in_sizes, int n_in,
                              void* d_out, int out_size)
{
    const float* s0      = (const float*)d_in[0];
    const float* eps     = (const float*)d_in[1];
    const float* enc_w1  = (const float*)d_in[2];
    const float* enc_b1  = (const float*)d_in[3];
    const float* enc_w2  = (const float*)d_in[4];
    const float* enc_b2  = (const float*)d_in[5];
    const float* zmu_w   = (const float*)d_in[6];
    const float* zmu_b   = (const float*)d_in[7];
    const float* zls_w   = (const float*)d_in[8];
    const float* zls_b   = (const float*)d_in[9];
    const float* mu_w1   = (const float*)d_in[10];
    const float* mu_b1   = (const float*)d_in[11];
    const float* mu_w2   = (const float*)d_in[12];
    const float* mu_b2   = (const float*)d_in[13];
    const float* mu_w3   = (const float*)d_in[14];
    const float* mu_b3   = (const float*)d_in[15];
    const float* sig_w1  = (const float*)d_in[16];
    const float* sig_b1  = (const float*)d_in[17];
    const float* sig_w2  = (const float*)d_in[18];
    const float* sig_b2  = (const float*)d_in[19];
    const float* sig_w3  = (const float*)d_in[20];
    const float* sig_b3  = (const float*)d_in[21];
    const float* risk_w1 = (const float*)d_in[22];
    const float* risk_b1 = (const float*)d_in[23];
    const float* risk_w2 = (const float*)d_in[24];
    const float* risk_b2 = (const float*)d_in[25];
    const float* risk_w3 = (const float*)d_in[26];
    const float* risk_b3 = (const float*)d_in[27];

    const int SMEM_BYTES = (80 + 2 * HID) * XROW * (int)sizeof(float);  // 85,248 B
    cudaFuncSetAttribute(score_kernel, cudaFuncAttributeMaxDynamicSharedMemorySize, SMEM_BYTES);

    encoder_kernel<<<BB, 256>>>(s0, enc_w1, enc_b1, enc_w2, enc_b2,
                                zmu_w, zmu_b, zls_w, zls_b);

    for (int i = 0; i < NITER; i++) {
        score_kernel<<<BB * (SS / TILE), 256, SMEM_BYTES>>>(i, s0, eps,
            mu_w1, mu_b1, mu_w2, mu_b2, mu_w3, mu_b3,
            sig_w1, sig_b1, sig_w2, sig_b2, sig_w3, sig_b3,
            risk_w1, risk_b1, risk_w2, risk_b2, risk_w3, risk_b3);
        topk_kernel<<<BB, 256>>>(i == NITER - 1 ? 1 : 0, (float*)d_out);
    }
}

// round 5
// speedup vs baseline: 2.6018x; 1.0659x over previous
#include <cuda_runtime.h>
#include <math.h>

#define BB    256
#define SS    512
#define OBS   64
#define ZD    16
#define HID   256
#define TPD   128      // T*PD
#define NITER 4
#define NEL   64
#define TILE  64
#define XROW  68       // smem row stride in floats (272B, multiple of 16B)
#define NTHR  512

// ---- packed f32x2 helpers ----
#define PACK2(dst, lo, hi) asm("mov.b64 %0, {%1, %2};" : "=l"(dst) : "f"(lo), "f"(hi))
#define UNPACK2(lo, hi, src) asm("mov.b64 {%0, %1}, %2;" : "=f"(lo), "=f"(hi) : "l"(src))
#define FMA2(acc, a, b) asm("fma.rn.f32x2 %0, %1, %2, %0;" : "+l"(acc) : "l"(a), "l"(b))

// ---------------- device scratch (no allocs allowed) ----------------
__device__ float g_mu[BB * ZD];
__device__ float g_std[BB * ZD];
__device__ float g_best_score[BB];
__device__ float g_best_z[BB * ZD];
__device__ float g_score[BB * SS];
__device__ float g_z[(size_t)BB * SS * ZD];
__device__ float g_base_mu[BB * HID];
__device__ float g_base_risk[BB * HID];

// ---------------- encoder + per-b layer1 base vectors ----------------
__global__ void encoder_kernel(const float* __restrict__ s0,
                               const float* __restrict__ enc_w1, const float* __restrict__ enc_b1,
                               const float* __restrict__ enc_w2, const float* __restrict__ enc_b2,
                               const float* __restrict__ zmu_w,  const float* __restrict__ zmu_b,
                               const float* __restrict__ zls_w,  const float* __restrict__ zls_b,
                               const float* __restrict__ mu_w1,  const float* __restrict__ mu_b1,
                               const float* __restrict__ risk_w1, const float* __restrict__ risk_b1)
{
    __shared__ float s0s[OBS];
    __shared__ float h1[HID];
    __shared__ float h2[HID];
    int b = blockIdx.x;
    int t = threadIdx.x;

    if (t < OBS) s0s[t] = s0[b * OBS + t];
    __syncthreads();

    // base vectors: s0-part of mu/risk layer1 (row-independent)
    {
        float bm = mu_b1[t], br = risk_b1[t];
        for (int k = 0; k < OBS; k++) {
            float sv = s0s[k];
            bm += sv * mu_w1[k * HID + t];
            br += sv * risk_w1[k * HID + t];
        }
        g_base_mu[b * HID + t]   = bm;
        g_base_risk[b * HID + t] = br;
    }

    float a = enc_b1[t];
    for (int k = 0; k < OBS; k++) a += s0s[k] * enc_w1[k * HID + t];
    h1[t] = fmaxf(a, 0.f);
    __syncthreads();

    a = enc_b2[t];
    for (int k = 0; k < HID; k++) a += h1[k] * enc_w2[k * HID + t];
    h2[t] = fmaxf(a, 0.f);
    __syncthreads();

    if (t < ZD) {
        float m = zmu_b[t], ls = zls_b[t];
        for (int k = 0; k < HID; k++) {
            float hv = h2[k];
            m  += hv * zmu_w[k * ZD + t];
            ls += hv * zls_w[k * ZD + t];
        }
        ls = fminf(fmaxf(ls, -4.f), 2.f);
        g_mu[b * ZD + t]     = m;
        g_std[b * ZD + t]    = expf(ls);
        g_best_z[b * ZD + t] = m;
    }
    if (t == 0) g_best_score[b] = -INFINITY;
}

// ---------------- fused tile GEMM, 2 cols x 16 rows per thread (512 thr, TILE=64) ----------------
// out[j][r] = act(bias[j] + sum_k xs[k][r]*W[k][j])
template<int K, bool DO_RELU>
__device__ __forceinline__ void gemm_tile(const float* __restrict__ xs,   // smem [K][XROW]
                                          const float* __restrict__ W,    // global [K][256]
                                          const float* __restrict__ bias, // global/scratch [256]
                                          float* __restrict__ outbuf)     // smem [256][XROW]
{
    const int t  = threadIdx.x;
    const int j0 = t & 127;
    const int j1 = j0 + 128;
    const int rg = t >> 7;                    // rows [rg*16, rg*16+16)
    const float* xbase = xs + rg * 16;

    unsigned long long accA[8], accB[8];
    {
        float b0 = bias[j0], b1 = bias[j1];
        unsigned long long b02, b12; PACK2(b02, b0, b0); PACK2(b12, b1, b1);
#pragma unroll
        for (int r = 0; r < 8; r++) { accA[r] = b02; accB[r] = b12; }
    }

    constexpr int PF = 8;
    float wa[PF], wb[PF];
#pragma unroll
    for (int p = 0; p < PF; p++) {
        wa[p] = (p < K) ? W[p * HID + j0] : 0.f;
        wb[p] = (p < K) ? W[p * HID + j1] : 0.f;
    }

#pragma unroll 8
    for (int k = 0; k < K; k++) {
        float wca = wa[k & 7], wcb = wb[k & 7];
        int kn = k + PF;
        if (kn < K) { wa[k & 7] = W[kn * HID + j0]; wb[k & 7] = W[kn * HID + j1]; }
        unsigned long long w2a, w2b; PACK2(w2a, wca, wca); PACK2(w2b, wcb, wcb);
        const ulonglong2* xr = reinterpret_cast<const ulonglong2*>(xbase + k * XROW);
#pragma unroll
        for (int r4 = 0; r4 < 4; r4++) {
            ulonglong2 v = xr[r4];
            FMA2(accA[r4 * 2 + 0], v.x, w2a);
            FMA2(accA[r4 * 2 + 1], v.y, w2a);
            FMA2(accB[r4 * 2 + 0], v.x, w2b);
            FMA2(accB[r4 * 2 + 1], v.y, w2b);
        }
    }

    float* o0 = outbuf + j0 * XROW + rg * 16;
    float* o1 = outbuf + j1 * XROW + rg * 16;
#pragma unroll
    for (int r2 = 0; r2 < 8; r2++) {
        float lo, hi;
        UNPACK2(lo, hi, accA[r2]);
        if (DO_RELU) { lo = fmaxf(lo, 0.f); hi = fmaxf(hi, 0.f); }
        o0[r2 * 2 + 0] = lo; o0[r2 * 2 + 1] = hi;
        UNPACK2(lo, hi, accB[r2]);
        if (DO_RELU) { lo = fmaxf(lo, 0.f); hi = fmaxf(hi, 0.f); }
        o1[r2 * 2 + 0] = lo; o1[r2 * 2 + 1] = hi;
    }
}

// ---------------- per-sample score ----------------
__global__ void __launch_bounds__(NTHR, 1) score_kernel(int iter,
    const float* __restrict__ s0,  const float* __restrict__ eps,
    const float* __restrict__ mu_w1,
    const float* __restrict__ mu_w2,  const float* __restrict__ mu_b2,
    const float* __restrict__ mu_w3,  const float* __restrict__ mu_b3,
    const float* __restrict__ sig_w1, const float* __restrict__ sig_b1,
    const float* __restrict__ sig_w2, const float* __restrict__ sig_b2,
    const float* __restrict__ sig_w3, const float* __restrict__ sig_b3,
    const float* __restrict__ risk_w1,
    const float* __restrict__ risk_w2, const float* __restrict__ risk_b2,
    const float* __restrict__ risk_w3, const float* __restrict__ risk_b3)
{
    extern __shared__ float smem[];
    float* xs   = smem;                       // [16][XROW]  (z only)
    float* bufA = smem + ZD * XROW;           // [256][XROW]
    float* bufB = bufA + HID * XROW;          // [256][XROW]

    __shared__ float mu_s[ZD], std_s[ZD];
    __shared__ float m_s[2 * TILE];
    __shared__ float red_s[NTHR];
    __shared__ float intent_s[TILE], agency_s[TILE];

    int bidx   = blockIdx.x;
    int b      = bidx >> 3;                   // SS/TILE = 8
    int s_base = (bidx & 7) * TILE;
    int t      = threadIdx.x;

    if (t < ZD) { mu_s[t] = g_mu[b * ZD + t]; std_s[t] = g_std[b * ZD + t]; }
    __syncthreads();

    // stage z transposed into smem, write z to global (coalesced)
    for (int idx = t; idx < ZD * TILE; idx += NTHR) {
        int d = idx & 15;
        int r = idx >> 4;
        float e = eps[((((size_t)iter * BB + b) * SS) + s_base + r) * ZD + d];
        float v = mu_s[d] + std_s[d] * e;
        g_z[((size_t)(b * SS + s_base + r)) * ZD + d] = v;
        xs[d * XROW + r] = v;
    }
    __syncthreads();

    // ---- mu path ----
    gemm_tile<ZD, true>(xs, mu_w1 + OBS * HID, g_base_mu + b * HID, bufA);
    __syncthreads();
    gemm_tile<HID, true>(bufA, mu_w2, mu_b2, bufB);
    __syncthreads();
    {   // head: cols 126,127 of mu_w3; 2c x 64r, k split over 4 segs
        int r = t & 63, c = (t >> 6) & 1, seg = t >> 7;
        const float* wc = mu_w3 + (TPD - 2) + c;
        float acc = 0.f;
        int k0 = seg * 64;
        for (int k = k0; k < k0 + 64; k++) acc += bufB[k * XROW + r] * wc[k * TPD];
        red_s[t] = acc;
    }
    __syncthreads();
    if (t < 2 * TILE) {
        int r = t & 63, c = t >> 6;
        int i0 = c * 64 + r;
        m_s[c * TILE + r] = mu_b3[(TPD - 2) + c] + red_s[i0] + red_s[i0 + 128] + red_s[i0 + 256] + red_s[i0 + 384];
    }
    __syncthreads();
    if (t < TILE) {
        float g0 = s0[b * OBS + 2];
        float g1 = s0[b * OBS + 3];
        float d0 = m_s[t] - g0;
        float d1 = m_s[TILE + t] - g1;
        intent_s[t] = d0 * d0 + d1 * d1;
    }
    __syncthreads();

    // ---- sigma path ----
    gemm_tile<ZD, true>(xs, sig_w1, sig_b1, bufA);
    __syncthreads();
    gemm_tile<HID, true>(bufA, sig_w2, sig_b2, bufB);
    __syncthreads();
    {   // layer3: 128 cols x 64 rows; 2 cols x 8 rows per thread
        int j0 = t & 63;
        int j1 = j0 + 64;
        int rg = t >> 6;                      // rows [rg*8, rg*8+8)
        const float* base = bufB + rg * 8;
        unsigned long long accA[4], accB[4];
        {
            float b0 = sig_b3[j0], b1 = sig_b3[j1];
            unsigned long long b02, b12; PACK2(b02, b0, b0); PACK2(b12, b1, b1);
#pragma unroll
            for (int r = 0; r < 4; r++) { accA[r] = b02; accB[r] = b12; }
        }
        constexpr int PF = 8;
        float wa[PF], wb[PF];
#pragma unroll
        for (int p = 0; p < PF; p++) { wa[p] = sig_w3[p * TPD + j0]; wb[p] = sig_w3[p * TPD + j1]; }
#pragma unroll 8
        for (int k = 0; k < HID; k++) {
            float wca = wa[k & 7], wcb = wb[k & 7];
            int kn = k + PF;
            if (kn < HID) { wa[k & 7] = sig_w3[kn * TPD + j0]; wb[k & 7] = sig_w3[kn * TPD + j1]; }
            unsigned long long w2a, w2b; PACK2(w2a, wca, wca); PACK2(w2b, wcb, wcb);
            const ulonglong2* xr = reinterpret_cast<const ulonglong2*>(base + k * XROW);
#pragma unroll
            for (int r4 = 0; r4 < 2; r4++) {
                ulonglong2 v = xr[r4];
                FMA2(accA[r4 * 2 + 0], v.x, w2a);
                FMA2(accA[r4 * 2 + 1], v.y, w2a);
                FMA2(accB[r4 * 2 + 0], v.x, w2b);
                FMA2(accB[r4 * 2 + 1], v.y, w2b);
            }
        }
        float* o0 = bufA + j0 * XROW + rg * 8;
        float* o1 = bufA + j1 * XROW + rg * 8;
#pragma unroll
        for (int r2 = 0; r2 < 4; r2++) {
            float lo, hi;
            UNPACK2(lo, hi, accA[r2]);
            o0[r2 * 2 + 0] = fminf(fmaxf(lo, -4.f), 3.f);
            o0[r2 * 2 + 1] = fminf(fmaxf(hi, -4.f), 3.f);
            UNPACK2(lo, hi, accB[r2]);
            o1[r2 * 2 + 0] = fminf(fmaxf(lo, -4.f), 3.f);
            o1[r2 * 2 + 1] = fminf(fmaxf(hi, -4.f), 3.f);
        }
    }
    __syncthreads();
    {   // agency: reduce 128 cols, 8 groups of 16 cols
        int r = t & 63, g = t >> 6;
        float sum = 0.f;
        for (int j = g * 16; j < g * 16 + 16; j++) sum += bufA[j * XROW + r];
        red_s[t] = sum;
    }
    __syncthreads();
    if (t < TILE) {
        float sum = 0.f;
#pragma unroll
        for (int g = 0; g < 8; g++) sum += red_s[t + g * 64];
        agency_s[t] = -sum * (1.f / TPD);
    }
    __syncthreads();

    // ---- risk path ----
    gemm_tile<ZD, true>(xs, risk_w1 + OBS * HID, g_base_risk + b * HID, bufA);
    __syncthreads();
    gemm_tile<HID, true>(bufA, risk_w2, risk_b2, bufB);
    __syncthreads();
    {   // layer3: 64 outputs, k split over 8 segs of 32
        int r = t & 63, seg = t >> 6;
        float acc = 0.f;
        int k0 = seg * 32;
        for (int k = k0; k < k0 + 32; k++) acc += bufB[k * XROW + r] * risk_w3[k];
        red_s[t] = acc;
    }
    __syncthreads();
    if (t < TILE) {
        float acc = risk_b3[0];
#pragma unroll
        for (int p = 0; p < 8; p++) acc += red_s[t + p * 64];
        float risk = 1.f / (1.f + expf(-acc));
        float score = -intent_s[t] + 0.5f * agency_s[t] - risk;
        g_score[b * SS + s_base + t] = score;
    }
}

// ---------------- top-k + CEM update ----------------
__global__ void topk_kernel(int write_out, float* __restrict__ out)
{
    __shared__ float keys[SS];
    __shared__ int   ids[SS];
    __shared__ float ps[16 * ZD];
    __shared__ float mean_s[ZD];
    __shared__ int   flag_s, bidx_s;

    int b = blockIdx.x;
    int t = threadIdx.x;

    keys[t]       = g_score[b * SS + t];       ids[t]       = t;
    keys[t + 256] = g_score[b * SS + t + 256]; ids[t + 256] = t + 256;

    // bitonic sort ascending (512 elems, 256 threads)
    for (int k2 = 2; k2 <= SS; k2 <<= 1)
        for (int j = k2 >> 1; j > 0; j >>= 1) {
            __syncthreads();
            int i = ((t & ~(j - 1)) << 1) | (t & (j - 1));
            int p = i | j;
            bool up = ((i & k2) == 0);
            float a = keys[i], c = keys[p];
            if ((a > c) == up) {
                keys[i] = c; keys[p] = a;
                int tmp = ids[i]; ids[i] = ids[p]; ids[p] = tmp;
            }
        }
    __syncthreads();

    // elite mean (top-64 = positions [448, 512))
    int d = t & 15, part = t >> 4;
    float sum = 0.f;
    for (int e = part * 4; e < part * 4 + 4; e++) {
        int si = ids[SS - NEL + e];
        sum += g_z[((size_t)(b * SS + si)) * ZD + d];
    }
    ps[part * ZD + d] = sum;
    __syncthreads();
    if (t < ZD) {
        float m = 0.f;
        for (int p2 = 0; p2 < 16; p2++) m += ps[p2 * ZD + t];
        mean_s[t] = m * (1.f / NEL);
    }
    __syncthreads();

    // elite var (ddof=1)
    sum = 0.f;
    for (int e = part * 4; e < part * 4 + 4; e++) {
        int si = ids[SS - NEL + e];
        float v = g_z[((size_t)(b * SS + si)) * ZD + d] - mean_s[d];
        sum += v * v;
    }
    ps[part * ZD + d] = sum;
    __syncthreads();

    if (t == 0) {
        float v0 = keys[SS - 1];
        int better = v0 > g_best_score[b];
        flag_s = better; bidx_s = ids[SS - 1];
        if (better) g_best_score[b] = v0;
    }
    __syncthreads();

    if (t < ZD) {
        float var  = 0.f;
        for (int p2 = 0; p2 < 16; p2++) var += ps[p2 * ZD + t];
        float nstd = sqrtf(var * (1.f / (NEL - 1)));
        float nmu  = mean_s[t];
        float om = g_mu[b * ZD + t], os = g_std[b * ZD + t];
        g_mu[b * ZD + t]  = 0.25f * om + 0.75f * nmu;
        g_std[b * ZD + t] = fmaxf(0.25f * os + 0.75f * nstd, 0.2f);
        if (flag_s) g_best_z[b * ZD + t] = g_z[((size_t)(b * SS + bidx_s)) * ZD + t];
    }

    if (write_out) {
        __syncthreads();
        if (t < ZD)  out[b * 17 + t]  = g_best_z[b * ZD + t];
        if (t == ZD) out[b * 17 + ZD] = g_best_score[b];
    }
}

// ---------------- launch ----------------
extern "C" void kernel_launch(void* const* d_in, const int* in_sizes, int n_in,
                              void* d_out, int out_size)
{
    const float* s0      = (const float*)d_in[0];
    const float* eps     = (const float*)d_in[1];
    const float* enc_w1  = (const float*)d_in[2];
    const float* enc_b1  = (const float*)d_in[3];
    const float* enc_w2  = (const float*)d_in[4];
    const float* enc_b2  = (const float*)d_in[5];
    const float* zmu_w   = (const float*)d_in[6];
    const float* zmu_b   = (const float*)d_in[7];
    const float* zls_w   = (const float*)d_in[8];
    const float* zls_b   = (const float*)d_in[9];
    const float* mu_w1   = (const float*)d_in[10];
    const float* mu_b1   = (const float*)d_in[11];
    const float* mu_w2   = (const float*)d_in[12];
    const float* mu_b2   = (const float*)d_in[13];
    const float* mu_w3   = (const float*)d_in[14];
    const float* mu_b3   = (const float*)d_in[15];
    const float* sig_w1  = (const float*)d_in[16];
    const float* sig_b1  = (const float*)d_in[17];
    const float* sig_w2  = (const float*)d_in[18];
    const float* sig_b2  = (const float*)d_in[19];
    const float* sig_w3  = (const float*)d_in[20];
    const float* sig_b3  = (const float*)d_in[21];
    const float* risk_w1 = (const float*)d_in[22];
    const float* risk_b1 = (const float*)d_in[23];
    const float* risk_w2 = (const float*)d_in[24];
    const float* risk_b2 = (const float*)d_in[25];
    const float* risk_w3 = (const float*)d_in[26];
    const float* risk_b3 = (const float*)d_in[27];

    const int SMEM_BYTES = (ZD + 2 * HID) * XROW * (int)sizeof(float);  // 143,616 B
    cudaFuncSetAttribute(score_kernel, cudaFuncAttributeMaxDynamicSharedMemorySize, SMEM_BYTES);

    encoder_kernel<<<BB, 256>>>(s0, enc_w1, enc_b1, enc_w2, enc_b2,
                                zmu_w, zmu_b, zls_w, zls_b,
                                mu_w1, mu_b1, risk_w1, risk_b1);

    for (int i = 0; i < NITER; i++) {
        score_kernel<<<BB * (SS / TILE), NTHR, SMEM_BYTES>>>(i, s0, eps,
            mu_w1, mu_w2, mu_b2, mu_w3, mu_b3,
            sig_w1, sig_b1, sig_w2, sig_b2, sig_w3, sig_b3,
            risk_w1, risk_w2, risk_b2, risk_w3, risk_b3);
        topk_kernel<<<BB, 256>>>(i == NITER - 1 ? 1 : 0, (float*)d_out);
    }
}